// round 1
// baseline (speedup 1.0000x reference)
#include <cuda_runtime.h>

#define DIMC 768
#define SEQ  2048
#define BB   2
#define NH   12
#define HDD  64
#define MTOT (BB*SEQ)          // 4096 rows per stream
#define UNITS (2*BB*NH)        // 48 (stream, batch, head) attention units
// SCALE = 64^-0.5 = 0.125 ; fold into exp2: S*SCALE*log2(e)
#define C_EXP (0.125f * 1.4426950408889634f)

// ---------------- scratch (static device globals; no allocations) ----------
__device__ float g_xm[2u*MTOT*DIMC];          // mixed inputs for K projection
__device__ float g_q [UNITS*SEQ*HDD];
__device__ float g_k [UNITS*SEQ*HDD];
__device__ float g_v [UNITS*SEQ*HDD];
__device__ float g_o [UNITS*SEQ*HDD];

__device__ __forceinline__ float fexp2(float x) {
    float y; asm("ex2.approx.ftz.f32 %0, %1;" : "=f"(y) : "f"(x)); return y;
}

// ---------------- 1) mix inputs for the K projection ------------------------
__global__ void mix_kernel(const float* __restrict__ x1,
                           const float* __restrict__ x2,
                           const float* __restrict__ sp) {
    int i = blockIdx.x * 256 + threadIdx.x;
    float s = sp[0];
    float a = x1[i], b = x2[i];
    g_xm[i]                = (1.0f - s) * a + s * b;   // stream 0: (1-s)x1+s x2
    g_xm[MTOT*DIMC + i]    = (1.0f - s) * b + s * a;   // stream 1: (1-s)x2+s x1
}

// ---------------- 2) fused QKV projection GEMM ------------------------------
// Y[m,c] = sum_k X[m,k]*W[c,k] + bias[c], scattered to [unit][n][d] layout.
// 128x128 tile, BK=8, 256 threads, 8x8 microtile (split 4+4 with 64 offset).
__global__ __launch_bounds__(256)
void qkv_kernel(const float* __restrict__ x1, const float* __restrict__ x2,
                const float* __restrict__ Wq, const float* __restrict__ bq,
                const float* __restrict__ Wk, const float* __restrict__ bk,
                const float* __restrict__ Wv, const float* __restrict__ bv) {
    __shared__ float Xs[8][132];
    __shared__ float Ws[8][132];

    int z = blockIdx.z;          // 0..5
    int s = z / 3, which = z % 3;
    const float* xs = s ? x2 : x1;
    const float* X; const float* W; const float* bias; float* out;
    if (which == 0)      { X = xs;                               W = Wq; bias = bq; out = g_q; }
    else if (which == 1) { X = g_xm + (size_t)s * MTOT * DIMC;   W = Wk; bias = bk; out = g_k; }
    else                 { X = xs;                               W = Wv; bias = bv; out = g_v; }

    int m0 = blockIdx.y * 128, c0 = blockIdx.x * 128;
    int t = threadIdx.x, tx = t & 15, ty = t >> 4;
    int mi = t >> 1, k4 = (t & 1) * 4;

    float acc[8][8];
#pragma unroll
    for (int i = 0; i < 8; i++)
#pragma unroll
        for (int j = 0; j < 8; j++) acc[i][j] = 0.0f;

    for (int k0 = 0; k0 < DIMC; k0 += 8) {
        float4 xv = *(const float4*)(X + (size_t)(m0 + mi) * DIMC + k0 + k4);
        float4 wv = *(const float4*)(W + (size_t)(c0 + mi) * DIMC + k0 + k4);
        __syncthreads();
        Xs[k4+0][mi] = xv.x; Xs[k4+1][mi] = xv.y; Xs[k4+2][mi] = xv.z; Xs[k4+3][mi] = xv.w;
        Ws[k4+0][mi] = wv.x; Ws[k4+1][mi] = wv.y; Ws[k4+2][mi] = wv.z; Ws[k4+3][mi] = wv.w;
        __syncthreads();
#pragma unroll
        for (int kk = 0; kk < 8; kk++) {
            float4 a0 = *(const float4*)&Xs[kk][ty*4];
            float4 a1 = *(const float4*)&Xs[kk][64 + ty*4];
            float4 b0 = *(const float4*)&Ws[kk][tx*4];
            float4 b1 = *(const float4*)&Ws[kk][64 + tx*4];
            float av[8] = {a0.x,a0.y,a0.z,a0.w,a1.x,a1.y,a1.z,a1.w};
            float bw[8] = {b0.x,b0.y,b0.z,b0.w,b1.x,b1.y,b1.z,b1.w};
#pragma unroll
            for (int i = 0; i < 8; i++)
#pragma unroll
                for (int j = 0; j < 8; j++) acc[i][j] += av[i] * bw[j];
        }
    }

    // epilogue: scatter to [ (s*BB+b)*NH+h ][ n ][ d ]
#pragma unroll
    for (int i = 0; i < 8; i++) {
        int m = m0 + ty*4 + (i & 3) + ((i >> 2) << 6);
        int b = m >> 11, n = m & 2047;
#pragma unroll
        for (int jj = 0; jj < 2; jj++) {
            int c = c0 + tx*4 + jj*64;
            int h = c >> 6, d = c & 63;
            float4 r;
            r.x = acc[i][jj*4+0] + bias[c+0];
            r.y = acc[i][jj*4+1] + bias[c+1];
            r.z = acc[i][jj*4+2] + bias[c+2];
            r.w = acc[i][jj*4+3] + bias[c+3];
            *(float4*)(out + ((((size_t)(s*BB + b))*NH + h)*SEQ + n)*HDD + d) = r;
        }
    }
}

// ---------------- 3) flash attention (per unit, 128-query blocks) -----------
// smem: Qs[d][r] (64x132), Ps[c][r] (64x132, XOR-swizzled),
//       Ks[d][c] (64x68, XOR-swizzled), Vs[c][d] (64x68)
#define ATT_SMEM ((2*64*132 + 2*64*68) * 4)

__global__ __launch_bounds__(256, 2)
void attn_kernel() {
    extern __shared__ float sm[];
    float* Qs = sm;                    // 64*132
    float* Ps = Qs + 64*132;           // 64*132
    float* Ks = Ps + 64*132;           // 64*68
    float* Vs = Ks + 64*68;            // 64*68

    int unit = blockIdx.y;
    const float* Qg = g_q + (size_t)unit*SEQ*HDD + (size_t)blockIdx.x*128*HDD;
    const float* Kg = g_k + (size_t)unit*SEQ*HDD;
    const float* Vg = g_v + (size_t)unit*SEQ*HDD;
    float*       Og = g_o + (size_t)unit*SEQ*HDD + (size_t)blockIdx.x*128*HDD;

    int t = threadIdx.x, tx = t & 15, ty = t >> 4;

    // load Q tile 128x64 transposed -> Qs[d][r] (one-time cost)
#pragma unroll
    for (int it = 0; it < 8; it++) {
        int idx = it*256 + t;
        int r = idx >> 4, d4 = (idx & 15) * 4;
        float4 v = *(const float4*)(Qg + r*64 + d4);
        Qs[(d4+0)*132 + r] = v.x;
        Qs[(d4+1)*132 + r] = v.y;
        Qs[(d4+2)*132 + r] = v.z;
        Qs[(d4+3)*132 + r] = v.w;
    }

    float m_i[8], l_i[8], acc[8][4];
#pragma unroll
    for (int i = 0; i < 8; i++) {
        m_i[i] = -1e30f; l_i[i] = 0.0f;
#pragma unroll
        for (int j = 0; j < 4; j++) acc[i][j] = 0.0f;
    }

    for (int kt = 0; kt < 32; kt++) {
        __syncthreads();   // previous AV done -> Ks/Vs/Ps reusable; Q store visible
        // load K (transposed+swizzled) and V (natural) tiles
#pragma unroll
        for (int it = 0; it < 4; it++) {
            int idx = it*256 + t;
            int c = idx >> 4, d4 = (idx & 15) * 4;
            float4 kv = *(const float4*)(Kg + (size_t)(kt*64 + c)*64 + d4);
            int pc = c ^ d4;                 // XOR swizzle by d-group
            Ks[(d4+0)*68 + pc] = kv.x;
            Ks[(d4+1)*68 + pc] = kv.y;
            Ks[(d4+2)*68 + pc] = kv.z;
            Ks[(d4+3)*68 + pc] = kv.w;
            float4 vv = *(const float4*)(Vg + (size_t)(kt*64 + c)*64 + d4);
            *(float4*)&Vs[c*68 + d4] = vv;
        }
        __syncthreads();   // tiles ready

        // S = Q K^T  (raw, scale folded into exp2)
        float S[8][4];
#pragma unroll
        for (int i = 0; i < 8; i++)
#pragma unroll
            for (int j = 0; j < 4; j++) S[i][j] = 0.0f;

#pragma unroll 8
        for (int dd = 0; dd < 64; dd++) {
            float4 a0 = *(const float4*)&Qs[dd*132 + ty*4];
            float4 a1 = *(const float4*)&Qs[dd*132 + 64 + ty*4];
            float4 b  = *(const float4*)&Ks[dd*68 + ((tx*4) ^ (dd & 60))];
            float av[8] = {a0.x,a0.y,a0.z,a0.w,a1.x,a1.y,a1.z,a1.w};
            float bw[4] = {b.x,b.y,b.z,b.w};
#pragma unroll
            for (int i = 0; i < 8; i++)
#pragma unroll
                for (int j = 0; j < 4; j++) S[i][j] += av[i] * bw[j];
        }

        // online softmax + write P (swizzled c-major)
#pragma unroll
        for (int i = 0; i < 8; i++) {
            float mx = fmaxf(fmaxf(S[i][0], S[i][1]), fmaxf(S[i][2], S[i][3]));
#pragma unroll
            for (int o = 8; o; o >>= 1) mx = fmaxf(mx, __shfl_xor_sync(0xffffffffu, mx, o));
            float mnew  = fmaxf(m_i[i], mx);
            float alpha = fexp2((m_i[i] - mnew) * C_EXP);
            m_i[i] = mnew;
            float p[4]; float rs = 0.0f;
#pragma unroll
            for (int j = 0; j < 4; j++) { p[j] = fexp2((S[i][j] - mnew) * C_EXP); rs += p[j]; }
#pragma unroll
            for (int o = 8; o; o >>= 1) rs += __shfl_xor_sync(0xffffffffu, rs, o);
            l_i[i] = l_i[i] * alpha + rs;
#pragma unroll
            for (int j = 0; j < 4; j++) acc[i][j] *= alpha;
            int r = (i < 4) ? (ty*4 + i) : (64 + ty*4 + (i - 4));
#pragma unroll
            for (int j = 0; j < 4; j++)
                Ps[(tx*4 + j)*132 + (r ^ (tx*4))] = p[j];
        }
        __syncthreads();   // P visible

        // O += P V
#pragma unroll 8
        for (int c = 0; c < 64; c++) {
            int xr = c & 60;
            float4 p0 = *(const float4*)&Ps[c*132 + ((ty*4) ^ xr)];
            float4 p1 = *(const float4*)&Ps[c*132 + 64 + ((ty*4) ^ xr)];
            float4 vv = *(const float4*)&Vs[c*68 + tx*4];
            float pv[8] = {p0.x,p0.y,p0.z,p0.w,p1.x,p1.y,p1.z,p1.w};
            float vw[4] = {vv.x,vv.y,vv.z,vv.w};
#pragma unroll
            for (int i = 0; i < 8; i++)
#pragma unroll
                for (int j = 0; j < 4; j++) acc[i][j] += pv[i] * vw[j];
        }
    }

    // epilogue: O[r][d] = acc / l
#pragma unroll
    for (int i = 0; i < 8; i++) {
        int r = (i < 4) ? (ty*4 + i) : (64 + ty*4 + (i - 4));
        float inv = 1.0f / l_i[i];
        float4 o;
        o.x = acc[i][0]*inv; o.y = acc[i][1]*inv; o.z = acc[i][2]*inv; o.w = acc[i][3]*inv;
        *(float4*)(Og + r*64 + tx*4) = o;
    }
}

// ---------------- 4) output projection --------------------------------------
__global__ __launch_bounds__(256)
void oproj_kernel(const float* __restrict__ Wo, const float* __restrict__ bo,
                  float* __restrict__ out) {
    __shared__ float Xs[8][132];
    __shared__ float Ws[8][132];

    int s = blockIdx.z;
    int m0 = blockIdx.y * 128, c0 = blockIdx.x * 128;
    int t = threadIdx.x, tx = t & 15, ty = t >> 4;
    int mi = t >> 1, k4 = (t & 1) * 4;
    int m = m0 + mi, b = m >> 11, n = m & 2047;

    float acc[8][8];
#pragma unroll
    for (int i = 0; i < 8; i++)
#pragma unroll
        for (int j = 0; j < 8; j++) acc[i][j] = 0.0f;

    for (int k0 = 0; k0 < DIMC; k0 += 8) {
        int k = k0 + k4, h = k >> 6, d = k & 63;
        float4 xv = *(const float4*)(g_o + ((((size_t)(s*BB + b))*NH + h)*SEQ + n)*HDD + d);
        float4 wv = *(const float4*)(Wo + (size_t)(c0 + mi) * DIMC + k0 + k4);
        __syncthreads();
        Xs[k4+0][mi] = xv.x; Xs[k4+1][mi] = xv.y; Xs[k4+2][mi] = xv.z; Xs[k4+3][mi] = xv.w;
        Ws[k4+0][mi] = wv.x; Ws[k4+1][mi] = wv.y; Ws[k4+2][mi] = wv.z; Ws[k4+3][mi] = wv.w;
        __syncthreads();
#pragma unroll
        for (int kk = 0; kk < 8; kk++) {
            float4 a0 = *(const float4*)&Xs[kk][ty*4];
            float4 a1 = *(const float4*)&Xs[kk][64 + ty*4];
            float4 b0 = *(const float4*)&Ws[kk][tx*4];
            float4 b1 = *(const float4*)&Ws[kk][64 + tx*4];
            float av[8] = {a0.x,a0.y,a0.z,a0.w,a1.x,a1.y,a1.z,a1.w};
            float bw[8] = {b0.x,b0.y,b0.z,b0.w,b1.x,b1.y,b1.z,b1.w};
#pragma unroll
            for (int i = 0; i < 8; i++)
#pragma unroll
                for (int j = 0; j < 8; j++) acc[i][j] += av[i] * bw[j];
        }
    }

    float* outb = out + (size_t)s * MTOT * DIMC;
#pragma unroll
    for (int i = 0; i < 8; i++) {
        int mm = m0 + ty*4 + (i & 3) + ((i >> 2) << 6);
#pragma unroll
        for (int jj = 0; jj < 2; jj++) {
            int c = c0 + tx*4 + jj*64;
            float4 r;
            r.x = acc[i][jj*4+0] + bo[c+0];
            r.y = acc[i][jj*4+1] + bo[c+1];
            r.z = acc[i][jj*4+2] + bo[c+2];
            r.w = acc[i][jj*4+3] + bo[c+3];
            *(float4*)(outb + (size_t)mm * DIMC + c) = r;
        }
    }
}

// ---------------- launch -----------------------------------------------------
extern "C" void kernel_launch(void* const* d_in, const int* in_sizes, int n_in,
                              void* d_out, int out_size) {
    const float* x1 = (const float*)d_in[0];
    const float* x2 = (const float*)d_in[1];
    const float* Wq = (const float*)d_in[2];
    const float* bq = (const float*)d_in[3];
    const float* Wk = (const float*)d_in[4];
    const float* bk = (const float*)d_in[5];
    const float* Wv = (const float*)d_in[6];
    const float* bv = (const float*)d_in[7];
    const float* Wo = (const float*)d_in[8];
    const float* bo = (const float*)d_in[9];
    const float* cs = (const float*)d_in[10];

    mix_kernel<<<(MTOT * DIMC) / 256, 256>>>(x1, x2, cs);
    qkv_kernel<<<dim3(6, 32, 6), 256>>>(x1, x2, Wq, bq, Wk, bk, Wv, bv);

    cudaFuncSetAttribute(attn_kernel, cudaFuncAttributeMaxDynamicSharedMemorySize, ATT_SMEM);
    attn_kernel<<<dim3(16, 48), 256, ATT_SMEM>>>();

    oproj_kernel<<<dim3(6, 32, 2), 256>>>(Wo, bo, (float*)d_out);
}

// round 2
// speedup vs baseline: 1.2184x; 1.2184x over previous
#include <cuda_runtime.h>
#include <cuda_bf16.h>

#define DIMC 768
#define SEQ  2048
#define BB   2
#define NH   12
#define HDD  64
#define MTOT (BB*SEQ)          // 4096 rows per stream
#define UNITS (2*BB*NH)        // 48 attention units
#define C_EXP (0.125f * 1.4426950408889634f)
#define MD ((size_t)MTOT*DIMC)
#define WD ((size_t)DIMC*DIMC)

// ---------------- scratch (static device globals) ---------------------------
// activations hi/lo: mat 0=x1, 1=x2, 2=xm(stream0), 3=xm(stream1)
__device__ __nv_bfloat16 g_xhi[4*MTOT*DIMC];
__device__ __nv_bfloat16 g_xlo[4*MTOT*DIMC];
// weights hi/lo: mat 0=Wq,1=Wk,2=Wv,3=Wo   (row-major [c][k])
__device__ __nv_bfloat16 g_whi[4*DIMC*DIMC];
__device__ __nv_bfloat16 g_wlo[4*DIMC*DIMC];
// q/k/v in head layout, fp32 (consumed by SIMT attention)
__device__ float g_q [UNITS*SEQ*HDD];
__device__ float g_k [UNITS*SEQ*HDD];
__device__ float g_v [UNITS*SEQ*HDD];
// attention output hi/lo, row-major [s][m][k]
__device__ __nv_bfloat16 g_ohi[2*MTOT*DIMC];
__device__ __nv_bfloat16 g_olo[2*MTOT*DIMC];

__device__ __forceinline__ float fexp2(float x) {
    float y; asm("ex2.approx.ftz.f32 %0, %1;" : "=f"(y) : "f"(x)); return y;
}
__device__ __forceinline__ void split2(float v, __nv_bfloat16& h, __nv_bfloat16& l) {
    h = __float2bfloat16(v);
    l = __float2bfloat16(v - __bfloat162float(h));
}
__device__ __forceinline__ void cp16(void* s, const void* g) {
    unsigned a = (unsigned)__cvta_generic_to_shared(s);
    asm volatile("cp.async.cg.shared.global [%0], [%1], 16;\n" :: "r"(a), "l"(g));
}
__device__ __forceinline__ void mma16816(float* d, const unsigned* a, unsigned b0, unsigned b1) {
    asm volatile("mma.sync.aligned.m16n8k16.row.col.f32.bf16.bf16.f32 "
                 "{%0,%1,%2,%3}, {%4,%5,%6,%7}, {%8,%9}, {%0,%1,%2,%3};"
                 : "+f"(d[0]), "+f"(d[1]), "+f"(d[2]), "+f"(d[3])
                 : "r"(a[0]), "r"(a[1]), "r"(a[2]), "r"(a[3]), "r"(b0), "r"(b1));
}

// ---------------- 1) mix + convert activations ------------------------------
__global__ void mixcvt_kernel(const float* __restrict__ x1,
                              const float* __restrict__ x2,
                              const float* __restrict__ sp) {
    int i = blockIdx.x * 256 + threadIdx.x;
    float s = sp[0];
    float a = x1[i], b = x2[i];
    float m0 = (1.0f - s) * a + s * b;   // keys for stream 0
    float m1 = (1.0f - s) * b + s * a;   // keys for stream 1
    split2(a,  g_xhi[i],            g_xlo[i]);
    split2(b,  g_xhi[MD   + i],     g_xlo[MD   + i]);
    split2(m0, g_xhi[2*MD + i],     g_xlo[2*MD + i]);
    split2(m1, g_xhi[3*MD + i],     g_xlo[3*MD + i]);
}

// ---------------- 2) convert weights ----------------------------------------
__global__ void wcvt_kernel(const float* __restrict__ Wq, const float* __restrict__ Wk,
                            const float* __restrict__ Wv, const float* __restrict__ Wo) {
    int i = blockIdx.x * 256 + threadIdx.x;
    int mat = blockIdx.y;
    const float* W = (mat == 0) ? Wq : (mat == 1) ? Wk : (mat == 2) ? Wv : Wo;
    split2(W[i], g_whi[mat*WD + i], g_wlo[mat*WD + i]);
}

// ---------------- shared GEMM body: Y = A @ B^T + bias ----------------------
// A: [M x 768] bf16 hi/lo row-major; B: [768 x 768] bf16 hi/lo row-major ([c][k]).
// CTA tile 128x128, 8 warps (4 m-groups x 2 n-groups), warp tile 32x64.
// smem per buffer: Ah/Al/Bh/Bl, each 128 rows x 24 bf16 (48B rows -> stride 12
// words -> conflict-free fragment loads). cp.async double-buffered.
template<bool HEAD_SCATTER>
__device__ __forceinline__ void gemm_body(
    __nv_bfloat16* sm,
    const __nv_bfloat16* __restrict__ Ahi, const __nv_bfloat16* __restrict__ Alo,
    const __nv_bfloat16* __restrict__ Bhi, const __nv_bfloat16* __restrict__ Blo,
    const float* __restrict__ bias, float* __restrict__ out,
    int m0, int c0, int ubase)
{
    int t = threadIdx.x, lane = t & 31, w = t >> 5;
    int wm = w & 3, wn = w >> 2;          // wm: 32-row group, wn: 64-col group
    int g = lane >> 2, c = lane & 3;

    const __nv_bfloat16* Ah_g = Ahi + (size_t)m0 * DIMC;
    const __nv_bfloat16* Al_g = Alo + (size_t)m0 * DIMC;
    const __nv_bfloat16* Bh_g = Bhi + (size_t)c0 * DIMC;
    const __nv_bfloat16* Bl_g = Blo + (size_t)c0 * DIMC;

    float acc[2][8][4];
#pragma unroll
    for (int mt = 0; mt < 2; mt++)
#pragma unroll
        for (int nt = 0; nt < 8; nt++)
#pragma unroll
            for (int j = 0; j < 4; j++) acc[mt][nt][j] = 0.0f;

    int row = t >> 1, half = t & 1;
    int so = row * 24 + half * 8;

    // prologue: slab 0
    {
        size_t go = (size_t)row * DIMC + half * 8;
        __nv_bfloat16* b0 = sm;
        cp16(b0 + so,        Ah_g + go);
        cp16(b0 + 3072 + so, Al_g + go);
        cp16(b0 + 6144 + so, Bh_g + go);
        cp16(b0 + 9216 + so, Bl_g + go);
    }
    asm volatile("cp.async.commit_group;\n");

    for (int ks = 0; ks < 48; ks++) {
        if (ks < 47) {
            size_t go = (size_t)row * DIMC + (ks + 1) * 16 + half * 8;
            __nv_bfloat16* bf = sm + ((ks + 1) & 1) * 12288;
            cp16(bf + so,        Ah_g + go);
            cp16(bf + 3072 + so, Al_g + go);
            cp16(bf + 6144 + so, Bh_g + go);
            cp16(bf + 9216 + so, Bl_g + go);
        }
        asm volatile("cp.async.commit_group;\n");
        asm volatile("cp.async.wait_group 1;\n");
        __syncthreads();

        const unsigned* Aw  = (const unsigned*)(sm + (ks & 1) * 12288);
        const unsigned* Alw = Aw + 1536;
        const unsigned* Bw  = Aw + 3072;
        const unsigned* Blw = Aw + 4608;

        unsigned ah[2][4], al[2][4];
#pragma unroll
        for (int mt = 0; mt < 2; mt++) {
            int r = wm * 32 + mt * 16 + g;
            ah[mt][0] = Aw [r*12 + c];     ah[mt][1] = Aw [(r+8)*12 + c];
            ah[mt][2] = Aw [r*12 + c + 4]; ah[mt][3] = Aw [(r+8)*12 + c + 4];
            al[mt][0] = Alw[r*12 + c];     al[mt][1] = Alw[(r+8)*12 + c];
            al[mt][2] = Alw[r*12 + c + 4]; al[mt][3] = Alw[(r+8)*12 + c + 4];
        }
#pragma unroll
        for (int nt = 0; nt < 8; nt++) {
            int n = wn * 64 + nt * 8 + g;
            unsigned bh0 = Bw [n*12 + c], bh1 = Bw [n*12 + c + 4];
            unsigned bl0 = Blw[n*12 + c], bl1 = Blw[n*12 + c + 4];
            mma16816(acc[0][nt], ah[0], bh0, bh1);
            mma16816(acc[1][nt], ah[1], bh0, bh1);
            mma16816(acc[0][nt], ah[0], bl0, bl1);
            mma16816(acc[1][nt], ah[1], bl0, bl1);
            mma16816(acc[0][nt], al[0], bh0, bh1);
            mma16816(acc[1][nt], al[1], bh0, bh1);
        }
        __syncthreads();
    }

    // epilogue
#pragma unroll
    for (int mt = 0; mt < 2; mt++) {
#pragma unroll
        for (int nt = 0; nt < 8; nt++) {
            int r0 = m0 + wm * 32 + mt * 16 + g;
            int col = c0 + wn * 64 + nt * 8 + 2 * c;
            float bb0 = bias[col], bb1 = bias[col + 1];
            float* A4 = acc[mt][nt];
            if (HEAD_SCATTER) {
                int h = col >> 6, d = col & 63;
                {
                    int bi = r0 >> 11, n = r0 & 2047;
                    float2 v = make_float2(A4[0] + bb0, A4[1] + bb1);
                    *(float2*)&out[(((size_t)(ubase + bi*NH + h))*SEQ + n)*HDD + d] = v;
                }
                {
                    int r1 = r0 + 8;
                    int bi = r1 >> 11, n = r1 & 2047;
                    float2 v = make_float2(A4[2] + bb0, A4[3] + bb1);
                    *(float2*)&out[(((size_t)(ubase + bi*NH + h))*SEQ + n)*HDD + d] = v;
                }
            } else {
                float2 v0 = make_float2(A4[0] + bb0, A4[1] + bb1);
                float2 v1 = make_float2(A4[2] + bb0, A4[3] + bb1);
                *(float2*)&out[(size_t)r0 * DIMC + col]       = v0;
                *(float2*)&out[(size_t)(r0+8) * DIMC + col]   = v1;
            }
        }
    }
}

#define GEMM_SMEM (2 * 12288 * 2)   // 49152 bytes

// ---------------- 3) fused QKV projection (tensor cores) --------------------
__global__ __launch_bounds__(256, 2)
void qkv_mma(const float* __restrict__ bq, const float* __restrict__ bk,
             const float* __restrict__ bv) {
    extern __shared__ __nv_bfloat16 smx[];
    int z = blockIdx.z, s = z / 3, which = z % 3;
    int amat = (which == 1) ? (2 + s) : s;
    const __nv_bfloat16* Ahi = g_xhi + (size_t)amat * MD;
    const __nv_bfloat16* Alo = g_xlo + (size_t)amat * MD;
    const __nv_bfloat16* Bhi = g_whi + (size_t)which * WD;
    const __nv_bfloat16* Blo = g_wlo + (size_t)which * WD;
    const float* bias = (which == 0) ? bq : (which == 1) ? bk : bv;
    float* out = (which == 0) ? g_q : (which == 1) ? g_k : g_v;
    gemm_body<true>(smx, Ahi, Alo, Bhi, Blo, bias, out,
                    blockIdx.y * 128, blockIdx.x * 128, s * BB * NH);
}

// ---------------- 5) output projection (tensor cores) -----------------------
__global__ __launch_bounds__(256, 2)
void oproj_mma(const float* __restrict__ bo, float* __restrict__ out) {
    extern __shared__ __nv_bfloat16 smx[];
    int s = blockIdx.z;
    gemm_body<false>(smx, g_ohi + (size_t)s * MD, g_olo + (size_t)s * MD,
                     g_whi + 3 * WD, g_wlo + 3 * WD, bo, out + (size_t)s * MD,
                     blockIdx.y * 128, blockIdx.x * 128, 0);
}

// ---------------- 4) flash attention (fp32 SIMT, unchanged core) ------------
#define ATT_SMEM ((2*64*132 + 2*64*68) * 4)

__global__ __launch_bounds__(256, 2)
void attn_kernel() {
    extern __shared__ float smf[];
    float* Qs = smf;
    float* Ps = Qs + 64*132;
    float* Ks = Ps + 64*132;
    float* Vs = Ks + 64*68;

    int unit = blockIdx.y;
    const float* Qg = g_q + (size_t)unit*SEQ*HDD + (size_t)blockIdx.x*128*HDD;
    const float* Kg = g_k + (size_t)unit*SEQ*HDD;
    const float* Vg = g_v + (size_t)unit*SEQ*HDD;

    int t = threadIdx.x, tx = t & 15, ty = t >> 4;

#pragma unroll
    for (int it = 0; it < 8; it++) {
        int idx = it*256 + t;
        int r = idx >> 4, d4 = (idx & 15) * 4;
        float4 v = *(const float4*)(Qg + r*64 + d4);
        Qs[(d4+0)*132 + r] = v.x;
        Qs[(d4+1)*132 + r] = v.y;
        Qs[(d4+2)*132 + r] = v.z;
        Qs[(d4+3)*132 + r] = v.w;
    }

    float m_i[8], l_i[8], acc[8][4];
#pragma unroll
    for (int i = 0; i < 8; i++) {
        m_i[i] = -1e30f; l_i[i] = 0.0f;
#pragma unroll
        for (int j = 0; j < 4; j++) acc[i][j] = 0.0f;
    }

    for (int kt = 0; kt < 32; kt++) {
        __syncthreads();
#pragma unroll
        for (int it = 0; it < 4; it++) {
            int idx = it*256 + t;
            int cc = idx >> 4, d4 = (idx & 15) * 4;
            float4 kv = *(const float4*)(Kg + (size_t)(kt*64 + cc)*64 + d4);
            int pc = cc ^ d4;
            Ks[(d4+0)*68 + pc] = kv.x;
            Ks[(d4+1)*68 + pc] = kv.y;
            Ks[(d4+2)*68 + pc] = kv.z;
            Ks[(d4+3)*68 + pc] = kv.w;
            float4 vv = *(const float4*)(Vg + (size_t)(kt*64 + cc)*64 + d4);
            *(float4*)&Vs[cc*68 + d4] = vv;
        }
        __syncthreads();

        float S[8][4];
#pragma unroll
        for (int i = 0; i < 8; i++)
#pragma unroll
            for (int j = 0; j < 4; j++) S[i][j] = 0.0f;

#pragma unroll 8
        for (int dd = 0; dd < 64; dd++) {
            float4 a0 = *(const float4*)&Qs[dd*132 + ty*4];
            float4 a1 = *(const float4*)&Qs[dd*132 + 64 + ty*4];
            float4 b  = *(const float4*)&Ks[dd*68 + ((tx*4) ^ (dd & 60))];
            float av[8] = {a0.x,a0.y,a0.z,a0.w,a1.x,a1.y,a1.z,a1.w};
            float bw[4] = {b.x,b.y,b.z,b.w};
#pragma unroll
            for (int i = 0; i < 8; i++)
#pragma unroll
                for (int j = 0; j < 4; j++) S[i][j] += av[i] * bw[j];
        }

#pragma unroll
        for (int i = 0; i < 8; i++) {
            float mx = fmaxf(fmaxf(S[i][0], S[i][1]), fmaxf(S[i][2], S[i][3]));
#pragma unroll
            for (int o = 8; o; o >>= 1) mx = fmaxf(mx, __shfl_xor_sync(0xffffffffu, mx, o));
            float mnew  = fmaxf(m_i[i], mx);
            float alpha = fexp2((m_i[i] - mnew) * C_EXP);
            m_i[i] = mnew;
            float p[4]; float rs = 0.0f;
#pragma unroll
            for (int j = 0; j < 4; j++) { p[j] = fexp2((S[i][j] - mnew) * C_EXP); rs += p[j]; }
#pragma unroll
            for (int o = 8; o; o >>= 1) rs += __shfl_xor_sync(0xffffffffu, rs, o);
            l_i[i] = l_i[i] * alpha + rs;
#pragma unroll
            for (int j = 0; j < 4; j++) acc[i][j] *= alpha;
            int r = (i < 4) ? (ty*4 + i) : (64 + ty*4 + (i - 4));
#pragma unroll
            for (int j = 0; j < 4; j++)
                Ps[(tx*4 + j)*132 + (r ^ (tx*4))] = p[j];
        }
        __syncthreads();

#pragma unroll 8
        for (int cc = 0; cc < 64; cc++) {
            int xr = cc & 60;
            float4 p0 = *(const float4*)&Ps[cc*132 + ((ty*4) ^ xr)];
            float4 p1 = *(const float4*)&Ps[cc*132 + 64 + ((ty*4) ^ xr)];
            float4 vv = *(const float4*)&Vs[cc*68 + tx*4];
            float pv[8] = {p0.x,p0.y,p0.z,p0.w,p1.x,p1.y,p1.z,p1.w};
            float vw[4] = {vv.x,vv.y,vv.z,vv.w};
#pragma unroll
            for (int i = 0; i < 8; i++)
#pragma unroll
                for (int j = 0; j < 4; j++) acc[i][j] += pv[i] * vw[j];
        }
    }

    // epilogue: normalize and write bf16 hi/lo into [s][m][k] row-major
    int s_  = unit / (BB*NH);
    int bh  = unit % (BB*NH);
    int bi  = bh / NH, h = bh % NH;

    struct __align__(8) B4 { __nv_bfloat16 v[4]; };

#pragma unroll
    for (int i = 0; i < 8; i++) {
        int r = (i < 4) ? (ty*4 + i) : (64 + ty*4 + (i - 4));
        float inv = 1.0f / l_i[i];
        B4 hb, lb;
#pragma unroll
        for (int j = 0; j < 4; j++) split2(acc[i][j] * inv, hb.v[j], lb.v[j]);
        size_t off = (size_t)s_ * MD
                   + (size_t)(bi*SEQ + blockIdx.x*128 + r) * DIMC + h*64 + tx*4;
        *(B4*)(g_ohi + off) = hb;
        *(B4*)(g_olo + off) = lb;
    }
}

// ---------------- launch -----------------------------------------------------
extern "C" void kernel_launch(void* const* d_in, const int* in_sizes, int n_in,
                              void* d_out, int out_size) {
    const float* x1 = (const float*)d_in[0];
    const float* x2 = (const float*)d_in[1];
    const float* Wq = (const float*)d_in[2];
    const float* bq = (const float*)d_in[3];
    const float* Wk = (const float*)d_in[4];
    const float* bk = (const float*)d_in[5];
    const float* Wv = (const float*)d_in[6];
    const float* bv = (const float*)d_in[7];
    const float* Wo = (const float*)d_in[8];
    const float* bo = (const float*)d_in[9];
    const float* cs = (const float*)d_in[10];

    cudaFuncSetAttribute(qkv_mma,  cudaFuncAttributeMaxDynamicSharedMemorySize, GEMM_SMEM);
    cudaFuncSetAttribute(oproj_mma, cudaFuncAttributeMaxDynamicSharedMemorySize, GEMM_SMEM);
    cudaFuncSetAttribute(attn_kernel, cudaFuncAttributeMaxDynamicSharedMemorySize, ATT_SMEM);

    mixcvt_kernel<<<(MTOT * DIMC) / 256, 256>>>(x1, x2, cs);
    wcvt_kernel<<<dim3((DIMC * DIMC) / 256, 4), 256>>>(Wq, Wk, Wv, Wo);

    qkv_mma<<<dim3(6, 32, 6), 256, GEMM_SMEM>>>(bq, bk, bv);

    attn_kernel<<<dim3(16, 48), 256, ATT_SMEM>>>();

    oproj_mma<<<dim3(6, 32, 2), 256, GEMM_SMEM>>>(bo, (float*)d_out);
}

// round 3
// speedup vs baseline: 2.3618x; 1.9385x over previous
#include <cuda_runtime.h>
#include <cuda_bf16.h>

#define DIMC 768
#define SEQ  2048
#define BB   2
#define NH   12
#define HDD  64
#define MTOT (BB*SEQ)
#define UNITS (2*BB*NH)
#define C_EXP (0.125f * 1.4426950408889634f)
#define MD ((size_t)MTOT*DIMC)
#define WD ((size_t)DIMC*DIMC)

// ---------------- scratch ----------------------------------------------------
__device__ __nv_bfloat16 g_xhi[4*MTOT*DIMC];
__device__ __nv_bfloat16 g_xlo[4*MTOT*DIMC];
__device__ __nv_bfloat16 g_whi[4*DIMC*DIMC];
__device__ __nv_bfloat16 g_wlo[4*DIMC*DIMC];
// Q/K/V bf16 hi/lo in head layout [unit][token][64]
__device__ __nv_bfloat16 g_qh[UNITS*SEQ*HDD], g_ql[UNITS*SEQ*HDD];
__device__ __nv_bfloat16 g_kh[UNITS*SEQ*HDD], g_kl[UNITS*SEQ*HDD];
__device__ __nv_bfloat16 g_vh[UNITS*SEQ*HDD], g_vl[UNITS*SEQ*HDD];
// attention output hi/lo, row-major [s][m][k]
__device__ __nv_bfloat16 g_ohi[2*MTOT*DIMC];
__device__ __nv_bfloat16 g_olo[2*MTOT*DIMC];

__device__ __forceinline__ float fexp2(float x) {
    float y; asm("ex2.approx.ftz.f32 %0, %1;" : "=f"(y) : "f"(x)); return y;
}
__device__ __forceinline__ void split2(float v, __nv_bfloat16& h, __nv_bfloat16& l) {
    h = __float2bfloat16(v);
    l = __float2bfloat16(v - __bfloat162float(h));
}
// pack (a,b) into bf16x2 hi word + bf16x2 lo word (low half = a)
__device__ __forceinline__ void packsplit(float a, float b, unsigned& hi, unsigned& lo) {
    union { __nv_bfloat162 v; unsigned u; } h, l;
    h.v = __floats2bfloat162_rn(a, b);
    float2 f = __bfloat1622float2(h.v);
    l.v = __floats2bfloat162_rn(a - f.x, b - f.y);
    hi = h.u; lo = l.u;
}
__device__ __forceinline__ void cp16(void* s, const void* g) {
    unsigned a = (unsigned)__cvta_generic_to_shared(s);
    asm volatile("cp.async.cg.shared.global [%0], [%1], 16;\n" :: "r"(a), "l"(g));
}
__device__ __forceinline__ void cp16u(unsigned s, const void* g) {
    asm volatile("cp.async.cg.shared.global [%0], [%1], 16;\n" :: "r"(s), "l"(g));
}
__device__ __forceinline__ void commitg() { asm volatile("cp.async.commit_group;\n"); }
__device__ __forceinline__ void waitg1()  { asm volatile("cp.async.wait_group 1;\n"); }
__device__ __forceinline__ void waitg0()  { asm volatile("cp.async.wait_group 0;\n"); }

__device__ __forceinline__ void mma16816(float* d, const unsigned* a, unsigned b0, unsigned b1) {
    asm volatile("mma.sync.aligned.m16n8k16.row.col.f32.bf16.bf16.f32 "
                 "{%0,%1,%2,%3}, {%4,%5,%6,%7}, {%8,%9}, {%0,%1,%2,%3};"
                 : "+f"(d[0]), "+f"(d[1]), "+f"(d[2]), "+f"(d[3])
                 : "r"(a[0]), "r"(a[1]), "r"(a[2]), "r"(a[3]), "r"(b0), "r"(b1));
}
__device__ __forceinline__ void ldsm4(unsigned* r, unsigned a) {
    asm volatile("ldmatrix.sync.aligned.m8n8.x4.shared.b16 {%0,%1,%2,%3}, [%4];"
                 : "=r"(r[0]), "=r"(r[1]), "=r"(r[2]), "=r"(r[3]) : "r"(a));
}
__device__ __forceinline__ void ldsm2(unsigned& r0, unsigned& r1, unsigned a) {
    asm volatile("ldmatrix.sync.aligned.m8n8.x2.shared.b16 {%0,%1}, [%2];"
                 : "=r"(r0), "=r"(r1) : "r"(a));
}
__device__ __forceinline__ void ldsm2t(unsigned& r0, unsigned& r1, unsigned a) {
    asm volatile("ldmatrix.sync.aligned.m8n8.x2.trans.shared.b16 {%0,%1}, [%2];"
                 : "=r"(r0), "=r"(r1) : "r"(a));
}
// swizzled smem chunk offset (chunk = 16B; 8 chunks per 64-bf16 row)
__device__ __forceinline__ unsigned swz(int row, int j) {
    return (unsigned)((row * 8 + (j ^ (row & 7))) << 4);
}

// ---------------- 1) mix + convert activations ------------------------------
__global__ void mixcvt_kernel(const float* __restrict__ x1,
                              const float* __restrict__ x2,
                              const float* __restrict__ sp) {
    int i = blockIdx.x * 256 + threadIdx.x;
    float s = sp[0];
    float a = x1[i], b = x2[i];
    float m0 = (1.0f - s) * a + s * b;
    float m1 = (1.0f - s) * b + s * a;
    split2(a,  g_xhi[i],          g_xlo[i]);
    split2(b,  g_xhi[MD   + i],   g_xlo[MD   + i]);
    split2(m0, g_xhi[2*MD + i],   g_xlo[2*MD + i]);
    split2(m1, g_xhi[3*MD + i],   g_xlo[3*MD + i]);
}

// ---------------- 2) convert weights ----------------------------------------
__global__ void wcvt_kernel(const float* __restrict__ Wq, const float* __restrict__ Wk,
                            const float* __restrict__ Wv, const float* __restrict__ Wo) {
    int i = blockIdx.x * 256 + threadIdx.x;
    int mat = blockIdx.y;
    const float* W = (mat == 0) ? Wq : (mat == 1) ? Wk : (mat == 2) ? Wv : Wo;
    split2(W[i], g_whi[mat*WD + i], g_wlo[mat*WD + i]);
}

// ---------------- shared GEMM body ------------------------------------------
template<bool HEAD_SCATTER>
__device__ __forceinline__ void gemm_body(
    __nv_bfloat16* sm,
    const __nv_bfloat16* __restrict__ Ahi, const __nv_bfloat16* __restrict__ Alo,
    const __nv_bfloat16* __restrict__ Bhi, const __nv_bfloat16* __restrict__ Blo,
    const float* __restrict__ bias,
    float* __restrict__ outf,
    __nv_bfloat16* __restrict__ oh, __nv_bfloat16* __restrict__ ol,
    int m0, int c0, int ubase)
{
    int t = threadIdx.x, lane = t & 31, w = t >> 5;
    int wm = w & 3, wn = w >> 2;
    int g = lane >> 2, c = lane & 3;

    const __nv_bfloat16* Ah_g = Ahi + (size_t)m0 * DIMC;
    const __nv_bfloat16* Al_g = Alo + (size_t)m0 * DIMC;
    const __nv_bfloat16* Bh_g = Bhi + (size_t)c0 * DIMC;
    const __nv_bfloat16* Bl_g = Blo + (size_t)c0 * DIMC;

    float acc[2][8][4];
#pragma unroll
    for (int mt = 0; mt < 2; mt++)
#pragma unroll
        for (int nt = 0; nt < 8; nt++)
#pragma unroll
            for (int j = 0; j < 4; j++) acc[mt][nt][j] = 0.0f;

    int row = t >> 1, half = t & 1;
    int so = row * 24 + half * 8;

    {
        size_t go = (size_t)row * DIMC + half * 8;
        __nv_bfloat16* b0 = sm;
        cp16(b0 + so,        Ah_g + go);
        cp16(b0 + 3072 + so, Al_g + go);
        cp16(b0 + 6144 + so, Bh_g + go);
        cp16(b0 + 9216 + so, Bl_g + go);
    }
    commitg();

    for (int ks = 0; ks < 48; ks++) {
        if (ks < 47) {
            size_t go = (size_t)row * DIMC + (ks + 1) * 16 + half * 8;
            __nv_bfloat16* bf = sm + ((ks + 1) & 1) * 12288;
            cp16(bf + so,        Ah_g + go);
            cp16(bf + 3072 + so, Al_g + go);
            cp16(bf + 6144 + so, Bh_g + go);
            cp16(bf + 9216 + so, Bl_g + go);
        }
        commitg();
        waitg1();
        __syncthreads();

        const unsigned* Aw  = (const unsigned*)(sm + (ks & 1) * 12288);
        const unsigned* Alw = Aw + 1536;
        const unsigned* Bw  = Aw + 3072;
        const unsigned* Blw = Aw + 4608;

        unsigned ah[2][4], al[2][4];
#pragma unroll
        for (int mt = 0; mt < 2; mt++) {
            int r = wm * 32 + mt * 16 + g;
            ah[mt][0] = Aw [r*12 + c];     ah[mt][1] = Aw [(r+8)*12 + c];
            ah[mt][2] = Aw [r*12 + c + 4]; ah[mt][3] = Aw [(r+8)*12 + c + 4];
            al[mt][0] = Alw[r*12 + c];     al[mt][1] = Alw[(r+8)*12 + c];
            al[mt][2] = Alw[r*12 + c + 4]; al[mt][3] = Alw[(r+8)*12 + c + 4];
        }
#pragma unroll
        for (int nt = 0; nt < 8; nt++) {
            int n = wn * 64 + nt * 8 + g;
            unsigned bh0 = Bw [n*12 + c], bh1 = Bw [n*12 + c + 4];
            unsigned bl0 = Blw[n*12 + c], bl1 = Blw[n*12 + c + 4];
            mma16816(acc[0][nt], ah[0], bh0, bh1);
            mma16816(acc[1][nt], ah[1], bh0, bh1);
            mma16816(acc[0][nt], ah[0], bl0, bl1);
            mma16816(acc[1][nt], ah[1], bl0, bl1);
            mma16816(acc[0][nt], al[0], bh0, bh1);
            mma16816(acc[1][nt], al[1], bh0, bh1);
        }
        __syncthreads();
    }

#pragma unroll
    for (int mt = 0; mt < 2; mt++) {
#pragma unroll
        for (int nt = 0; nt < 8; nt++) {
            int r0 = m0 + wm * 32 + mt * 16 + g;
            int col = c0 + wn * 64 + nt * 8 + 2 * c;
            float bb0 = bias[col], bb1 = bias[col + 1];
            float* A4 = acc[mt][nt];
            if (HEAD_SCATTER) {
                int h = col >> 6, d = col & 63;
                {
                    int bi = r0 >> 11, n = r0 & 2047;
                    size_t off = (((size_t)(ubase + bi*NH + h))*SEQ + n)*HDD + d;
                    unsigned hw, lw; packsplit(A4[0] + bb0, A4[1] + bb1, hw, lw);
                    *(unsigned*)(oh + off) = hw;
                    *(unsigned*)(ol + off) = lw;
                }
                {
                    int r1 = r0 + 8;
                    int bi = r1 >> 11, n = r1 & 2047;
                    size_t off = (((size_t)(ubase + bi*NH + h))*SEQ + n)*HDD + d;
                    unsigned hw, lw; packsplit(A4[2] + bb0, A4[3] + bb1, hw, lw);
                    *(unsigned*)(oh + off) = hw;
                    *(unsigned*)(ol + off) = lw;
                }
            } else {
                float2 v0 = make_float2(A4[0] + bb0, A4[1] + bb1);
                float2 v1 = make_float2(A4[2] + bb0, A4[3] + bb1);
                *(float2*)&outf[(size_t)r0 * DIMC + col]     = v0;
                *(float2*)&outf[(size_t)(r0+8) * DIMC + col] = v1;
            }
        }
    }
}

#define GEMM_SMEM (2 * 12288 * 2)

// ---------------- 3) fused QKV projection -----------------------------------
__global__ __launch_bounds__(256, 2)
void qkv_mma(const float* __restrict__ bq, const float* __restrict__ bk,
             const float* __restrict__ bv) {
    extern __shared__ __nv_bfloat16 smx[];
    int z = blockIdx.z, s = z / 3, which = z % 3;
    int amat = (which == 1) ? (2 + s) : s;
    const __nv_bfloat16* Ahi = g_xhi + (size_t)amat * MD;
    const __nv_bfloat16* Alo = g_xlo + (size_t)amat * MD;
    const __nv_bfloat16* Bhi = g_whi + (size_t)which * WD;
    const __nv_bfloat16* Blo = g_wlo + (size_t)which * WD;
    const float* bias = (which == 0) ? bq : (which == 1) ? bk : bv;
    __nv_bfloat16* oh = (which == 0) ? g_qh : (which == 1) ? g_kh : g_vh;
    __nv_bfloat16* ol = (which == 0) ? g_ql : (which == 1) ? g_kl : g_vl;
    gemm_body<true>(smx, Ahi, Alo, Bhi, Blo, bias, nullptr, oh, ol,
                    blockIdx.y * 128, blockIdx.x * 128, s * BB * NH);
}

// ---------------- 5) output projection --------------------------------------
__global__ __launch_bounds__(256, 2)
void oproj_mma(const float* __restrict__ bo, float* __restrict__ out) {
    extern __shared__ __nv_bfloat16 smx[];
    int s = blockIdx.z;
    gemm_body<false>(smx, g_ohi + (size_t)s * MD, g_olo + (size_t)s * MD,
                     g_whi + 3 * WD, g_wlo + 3 * WD, bo, out + (size_t)s * MD,
                     nullptr, nullptr, blockIdx.y * 128, blockIdx.x * 128, 0);
}

// ---------------- 4) flash attention (tensor cores) -------------------------
// 8 warps x 16 query rows = 128-query block; 64-key tiles double-buffered.
// smem: stage s at s*32768: Kh(8K) Kl(8K) Vh(8K) Vl(8K).  Q staged in stage-1
// region (Qh @32768, Ql @49152) before the pipeline starts.
#define AT_SMEM 65536

__global__ __launch_bounds__(256, 1)
void attn_mma() {
    extern __shared__ char smc[];
    unsigned sbase = (unsigned)__cvta_generic_to_shared(smc);
    int t = threadIdx.x, lane = t & 31, w = t >> 5;
    int g = lane >> 2, cc = lane & 3;
    int unit = blockIdx.y, qblk = blockIdx.x;

    const __nv_bfloat16* Qh_g = g_qh + (size_t)unit*SEQ*HDD + (size_t)qblk*128*HDD;
    const __nv_bfloat16* Ql_g = g_ql + (size_t)unit*SEQ*HDD + (size_t)qblk*128*HDD;
    const __nv_bfloat16* Kh_g = g_kh + (size_t)unit*SEQ*HDD;
    const __nv_bfloat16* Kl_g = g_kl + (size_t)unit*SEQ*HDD;
    const __nv_bfloat16* Vh_g = g_vh + (size_t)unit*SEQ*HDD;
    const __nv_bfloat16* Vl_g = g_vl + (size_t)unit*SEQ*HDD;

    // ---- stage Q (128 rows x 8 chunks, hi+lo) into stage-1 region ----
    {
        int row = t >> 1, j0 = (t & 1) * 4;
#pragma unroll
        for (int jj = 0; jj < 4; jj++) {
            int j = j0 + jj;
            cp16u(sbase + 32768 + swz(row, j), Qh_g + row*64 + j*8);
            cp16u(sbase + 49152 + swz(row, j), Ql_g + row*64 + j*8);
        }
    }
    commitg(); waitg0();
    __syncthreads();

    // ---- Q fragments to registers ----
    unsigned qh[4][4], ql[4][4];
    int R0 = w * 16;
    {
        int mi = lane >> 3, rr = lane & 7;
#pragma unroll
        for (int kk = 0; kk < 4; kk++) {
            int rowq = R0 + (mi & 1) * 8 + rr;
            int jc = kk * 2 + (mi >> 1);
            unsigned a = sbase + 32768 + swz(rowq, jc);
            ldsm4(qh[kk], a);
            ldsm4(ql[kk], a + 16384);
        }
    }
    __syncthreads();

    float O[8][4];
#pragma unroll
    for (int nt = 0; nt < 8; nt++)
#pragma unroll
        for (int j = 0; j < 4; j++) O[nt][j] = 0.0f;
    float m0 = -1e30f, m1 = -1e30f, l0 = 0.0f, l1 = 0.0f;

    int krow = t >> 2, kj0 = (t & 3) * 2;

    // prologue: tile 0 -> stage 0
#pragma unroll
    for (int jj = 0; jj < 2; jj++) {
        int j = kj0 + jj;
        unsigned so = swz(krow, j);
        size_t go = (size_t)krow * 64 + j * 8;
        cp16u(sbase + so,         Kh_g + go);
        cp16u(sbase + 8192  + so, Kl_g + go);
        cp16u(sbase + 16384 + so, Vh_g + go);
        cp16u(sbase + 24576 + so, Vl_g + go);
    }
    commitg();

    for (int kt = 0; kt < 32; kt++) {
        if (kt < 31) {
            unsigned sb2 = sbase + ((kt + 1) & 1) * 32768;
#pragma unroll
            for (int jj = 0; jj < 2; jj++) {
                int j = kj0 + jj;
                unsigned so = swz(krow, j);
                size_t go = (size_t)((kt + 1) * 64 + krow) * 64 + j * 8;
                cp16u(sb2 + so,         Kh_g + go);
                cp16u(sb2 + 8192  + so, Kl_g + go);
                cp16u(sb2 + 16384 + so, Vh_g + go);
                cp16u(sb2 + 24576 + so, Vl_g + go);
            }
        }
        commitg();
        waitg1();
        __syncthreads();

        unsigned sb = sbase + (kt & 1) * 32768;

        // ---- S = Q K^T (3-mma hi/lo) ----
        float S[8][4];
#pragma unroll
        for (int nt = 0; nt < 8; nt++)
#pragma unroll
            for (int j = 0; j < 4; j++) S[nt][j] = 0.0f;

        {
            int rr = lane & 7, hf = (lane >> 3) & 1;
#pragma unroll
            for (int nt = 0; nt < 8; nt++) {
                int rowk = nt * 8 + rr;
#pragma unroll
                for (int kk = 0; kk < 4; kk++) {
                    unsigned ka = sb + swz(rowk, kk * 2 + hf);
                    unsigned bh0, bh1, bl0, bl1;
                    ldsm2(bh0, bh1, ka);
                    ldsm2(bl0, bl1, ka + 8192);
                    mma16816(S[nt], qh[kk], bh0, bh1);
                    mma16816(S[nt], qh[kk], bl0, bl1);
                    mma16816(S[nt], ql[kk], bh0, bh1);
                }
            }
        }

        // ---- online softmax ----
        float mx0 = -1e30f, mx1 = -1e30f;
#pragma unroll
        for (int nt = 0; nt < 8; nt++) {
            mx0 = fmaxf(mx0, fmaxf(S[nt][0], S[nt][1]));
            mx1 = fmaxf(mx1, fmaxf(S[nt][2], S[nt][3]));
        }
        mx0 = fmaxf(mx0, __shfl_xor_sync(0xffffffffu, mx0, 1));
        mx0 = fmaxf(mx0, __shfl_xor_sync(0xffffffffu, mx0, 2));
        mx1 = fmaxf(mx1, __shfl_xor_sync(0xffffffffu, mx1, 1));
        mx1 = fmaxf(mx1, __shfl_xor_sync(0xffffffffu, mx1, 2));
        float m0n = fmaxf(m0, mx0), m1n = fmaxf(m1, mx1);
        float al0 = fexp2((m0 - m0n) * C_EXP);
        float al1 = fexp2((m1 - m1n) * C_EXP);
        float mc0 = m0n * C_EXP, mc1 = m1n * C_EXP;
        l0 *= al0; l1 *= al1;
#pragma unroll
        for (int nt = 0; nt < 8; nt++) {
            float p0 = fexp2(fmaf(S[nt][0], C_EXP, -mc0));
            float p1 = fexp2(fmaf(S[nt][1], C_EXP, -mc0));
            float p2 = fexp2(fmaf(S[nt][2], C_EXP, -mc1));
            float p3 = fexp2(fmaf(S[nt][3], C_EXP, -mc1));
            l0 += p0 + p1; l1 += p2 + p3;
            S[nt][0] = p0; S[nt][1] = p1; S[nt][2] = p2; S[nt][3] = p3;
            O[nt][0] *= al0; O[nt][1] *= al0; O[nt][2] *= al1; O[nt][3] *= al1;
        }
        m0 = m0n; m1 = m1n;

        // ---- pack P into A-fragments (hi/lo) ----
        unsigned ph[4][4], pl[4][4];
#pragma unroll
        for (int tt = 0; tt < 4; tt++) {
            packsplit(S[2*tt][0],   S[2*tt][1],   ph[tt][0], pl[tt][0]);
            packsplit(S[2*tt][2],   S[2*tt][3],   ph[tt][1], pl[tt][1]);
            packsplit(S[2*tt+1][0], S[2*tt+1][1], ph[tt][2], pl[tt][2]);
            packsplit(S[2*tt+1][2], S[2*tt+1][3], ph[tt][3], pl[tt][3]);
        }

        // ---- O += P V  (V via ldmatrix.trans; 3-mma hi/lo) ----
        {
            int vlr = lane & 15;
#pragma unroll
            for (int tt = 0; tt < 4; tt++) {
                int rowv = tt * 16 + vlr;
#pragma unroll
                for (int nd = 0; nd < 8; nd++) {
                    unsigned va = sb + 16384 + swz(rowv, nd);
                    unsigned vh0, vh1, vl0, vl1;
                    ldsm2t(vh0, vh1, va);
                    ldsm2t(vl0, vl1, va + 8192);
                    mma16816(O[nd], ph[tt], vh0, vh1);
                    mma16816(O[nd], ph[tt], vl0, vl1);
                    mma16816(O[nd], pl[tt], vh0, vh1);
                }
            }
        }
        __syncthreads();
    }

    // ---- epilogue ----
    l0 += __shfl_xor_sync(0xffffffffu, l0, 1);
    l0 += __shfl_xor_sync(0xffffffffu, l0, 2);
    l1 += __shfl_xor_sync(0xffffffffu, l1, 1);
    l1 += __shfl_xor_sync(0xffffffffu, l1, 2);
    float inv0 = 1.0f / l0, inv1 = 1.0f / l1;

    int s_ = unit / (BB*NH);
    int bh_ = unit % (BB*NH);
    int bi = bh_ / NH, h = bh_ % NH;
    int tok0 = qblk * 128 + R0 + g;
    int tok1 = tok0 + 8;

#pragma unroll
    for (int nd = 0; nd < 8; nd++) {
        int d = nd * 8 + 2 * cc;
        unsigned hw, lw;
        size_t off0 = (size_t)s_ * MD + (size_t)(bi*SEQ + tok0) * DIMC + h*64 + d;
        packsplit(O[nd][0] * inv0, O[nd][1] * inv0, hw, lw);
        *(unsigned*)(g_ohi + off0) = hw;
        *(unsigned*)(g_olo + off0) = lw;
        size_t off1 = (size_t)s_ * MD + (size_t)(bi*SEQ + tok1) * DIMC + h*64 + d;
        packsplit(O[nd][2] * inv1, O[nd][3] * inv1, hw, lw);
        *(unsigned*)(g_ohi + off1) = hw;
        *(unsigned*)(g_olo + off1) = lw;
    }
}

// ---------------- launch -----------------------------------------------------
extern "C" void kernel_launch(void* const* d_in, const int* in_sizes, int n_in,
                              void* d_out, int out_size) {
    const float* x1 = (const float*)d_in[0];
    const float* x2 = (const float*)d_in[1];
    const float* Wq = (const float*)d_in[2];
    const float* bq = (const float*)d_in[3];
    const float* Wk = (const float*)d_in[4];
    const float* bk = (const float*)d_in[5];
    const float* Wv = (const float*)d_in[6];
    const float* bv = (const float*)d_in[7];
    const float* Wo = (const float*)d_in[8];
    const float* bo = (const float*)d_in[9];
    const float* cs = (const float*)d_in[10];

    cudaFuncSetAttribute(qkv_mma,   cudaFuncAttributeMaxDynamicSharedMemorySize, GEMM_SMEM);
    cudaFuncSetAttribute(oproj_mma, cudaFuncAttributeMaxDynamicSharedMemorySize, GEMM_SMEM);
    cudaFuncSetAttribute(attn_mma,  cudaFuncAttributeMaxDynamicSharedMemorySize, AT_SMEM);

    mixcvt_kernel<<<(MTOT * DIMC) / 256, 256>>>(x1, x2, cs);
    wcvt_kernel<<<dim3((DIMC * DIMC) / 256, 4), 256>>>(Wq, Wk, Wv, Wo);

    qkv_mma<<<dim3(6, 32, 6), 256, GEMM_SMEM>>>(bq, bk, bv);

    attn_mma<<<dim3(16, 48), 256, AT_SMEM>>>();

    oproj_mma<<<dim3(6, 32, 2), 256, GEMM_SMEM>>>(bo, (float*)d_out);
}